// round 5
// baseline (speedup 1.0000x reference)
#include <cuda_runtime.h>
#include <math.h>

#define B 192
#define D 2048
#define H 128
#define LOG2PI 1.8378770664093453f
#define IG 4   // i-rows per main-kernel block

// Scratch (device globals — no allocation allowed)
__device__ __align__(16) float g_h1[B * 2 * H];
__device__ __align__(16) float g_h2[B * 2 * H];
__device__ __align__(16) float g_mu[B * D];
__device__ __align__(16) float g_scale[B * D];
__device__ float g_lvpart[B * 8];

// ---------------------------------------------------------------------------
// Kernel 1: h1 = relu(q @ w1^T + b1), both heads (cols 0..127 mu, 128..255 lv).
// 8x4 register-tiled warps: warp computes 8 rows x 4 cols, lanes split K=2048.
// Weight L2 traffic halved vs 4-row version (each w row reused by 8 q rows).
// grid = (8 colgroups-of-8warps, 24 rowgroups) x 256 threads = 192 blocks.
// ---------------------------------------------------------------------------
__global__ void __launch_bounds__(256) gemm1_kernel(
    const float* __restrict__ q,
    const float* __restrict__ mw, const float* __restrict__ mb,
    const float* __restrict__ lw, const float* __restrict__ lb)
{
    int warp = threadIdx.x >> 5;
    int lane = threadIdx.x & 31;
    int cg   = blockIdx.x * 8 + warp;   // colgroup 0..63
    int row0 = blockIdx.y * 8;
    int col0 = cg * 4;

    const float* wbase;
    const float* bbase;
    int clocal;
    if (col0 < H) { wbase = mw; bbase = mb; clocal = col0;     }
    else          { wbase = lw; bbase = lb; clocal = col0 - H; }

    const float4* q4 = (const float4*)q;
    const float4* w4 = (const float4*)wbase;

    float acc[8][4];
    #pragma unroll
    for (int r = 0; r < 8; ++r)
        #pragma unroll
        for (int c = 0; c < 4; ++c) acc[r][c] = 0.f;

    #pragma unroll 4
    for (int it = 0; it < (D / 4) / 32; ++it) {   // 16 iters
        int k4 = lane + it * 32;
        float4 b[4];
        #pragma unroll
        for (int c = 0; c < 4; ++c) b[c] = w4[(size_t)(clocal + c) * (D / 4) + k4];
        #pragma unroll
        for (int r = 0; r < 8; ++r) {
            float4 a = q4[(size_t)(row0 + r) * (D / 4) + k4];
            #pragma unroll
            for (int c = 0; c < 4; ++c)
                acc[r][c] += a.x * b[c].x + a.y * b[c].y
                           + a.z * b[c].z + a.w * b[c].w;
        }
    }

    float bv[4];
    #pragma unroll
    for (int c = 0; c < 4; ++c) bv[c] = bbase[clocal + c];

    #pragma unroll
    for (int r = 0; r < 8; ++r)
        #pragma unroll
        for (int c = 0; c < 4; ++c) {
            float v = acc[r][c];
            #pragma unroll
            for (int o = 16; o; o >>= 1) v += __shfl_xor_sync(0xffffffffu, v, o);
            if (lane == 0)
                g_h1[(row0 + r) * 256 + col0 + c] = fmaxf(v + bv[c], 0.f);
        }
}

// ---------------------------------------------------------------------------
// Kernel 2: h2 = relu(h1 @ w2^T + b2). 8 rows per block (24 blocks).
// ---------------------------------------------------------------------------
__global__ void __launch_bounds__(256) gemm2_kernel(
    const float* __restrict__ mw, const float* __restrict__ mb,
    const float* __restrict__ lw, const float* __restrict__ lb)
{
    __shared__ float s[8][256];
    int row0 = blockIdx.x * 8;
    int tid = threadIdx.x;

    #pragma unroll
    for (int r = 0; r < 8; ++r)
        s[r][tid] = g_h1[(row0 + r) * 256 + tid];
    __syncthreads();

    const float* w;
    float bias;
    int hoff;
    if (tid < H) { w = mw + (size_t)tid * H;       bias = mb[tid];     hoff = 0; }
    else         { w = lw + (size_t)(tid - H) * H; bias = lb[tid - H]; hoff = H; }

    float acc[8];
    #pragma unroll
    for (int r = 0; r < 8; ++r) acc[r] = bias;

    #pragma unroll 8
    for (int k = 0; k < H; ++k) {
        float wv = w[k];
        #pragma unroll
        for (int r = 0; r < 8; ++r) acc[r] += s[r][hoff + k] * wv;
    }
    #pragma unroll
    for (int r = 0; r < 8; ++r)
        g_h2[(row0 + r) * 256 + tid] = fmaxf(acc[r], 0.f);
}

// ---------------------------------------------------------------------------
// Kernel 3: layer-3 for both heads, 8 rows per block, h2 half-rows in smem.
//   mu head  (bx 0..7):  g_mu = relu(...)
//   lv head  (bx 8..15): g_scale = exp(0.25*lv), deterministic partial sum(lv)
// grid = (16, 24) x 256. 32 FMA per float4 weight load.
// ---------------------------------------------------------------------------
__global__ void __launch_bounds__(256) gemm3_kernel(
    const float* __restrict__ mw, const float* __restrict__ mb,
    const float* __restrict__ lw, const float* __restrict__ lb)
{
    __shared__ float4 s4[8][32];       // 8 rows x 128 floats (one head half)
    __shared__ float red[8][8];

    int tid  = threadIdx.x;
    int row0 = blockIdx.y * 8;
    int head = blockIdx.x >> 3;        // 0 = mu, 1 = lv

    {   // 256 threads load 8 rows x 32 float4
        int r  = tid >> 5;
        int kk = tid & 31;
        s4[r][kk] = ((const float4*)(g_h2 + (row0 + r) * 256 + head * H))[kk];
    }
    __syncthreads();

    int d = (blockIdx.x & 7) * 256 + tid;         // 0..2047 within head
    const float* wrow = (head ? lw : mw) + (size_t)d * H;
    const float* bptr = head ? lb : mb;

    float acc[8];
    #pragma unroll
    for (int r = 0; r < 8; ++r) acc[r] = 0.f;

    #pragma unroll
    for (int kk = 0; kk < 32; ++kk) {
        float4 w = ((const float4*)wrow)[kk];
        #pragma unroll
        for (int r = 0; r < 8; ++r) {
            float4 h = s4[r][kk];
            acc[r] += w.x * h.x + w.y * h.y + w.z * h.z + w.w * h.w;
        }
    }
    float bias = bptr[d];

    if (!head) {
        #pragma unroll
        for (int r = 0; r < 8; ++r)
            g_mu[(size_t)(row0 + r) * D + d] = fmaxf(acc[r] + bias, 0.f);
    } else {
        int lane = tid & 31, wid = tid >> 5;
        #pragma unroll
        for (int r = 0; r < 8; ++r) {
            float v = fmaxf(acc[r] + bias, 0.f);
            g_scale[(size_t)(row0 + r) * D + d] = expf(0.25f * v);
            #pragma unroll
            for (int o = 16; o; o >>= 1) v += __shfl_xor_sync(0xffffffffu, v, o);
            if (lane == 0) red[wid][r] = v;
        }
        __syncthreads();
        if (tid == 0) {
            #pragma unroll
            for (int r = 0; r < 8; ++r) {
                float sum = 0.f;
                #pragma unroll
                for (int k = 0; k < 8; ++k) sum += red[k][r];
                g_lvpart[(row0 + r) * 8 + (blockIdx.x & 7)] = sum;
            }
        }
    }
}

// ---------------------------------------------------------------------------
// Kernel 4 (HBM-bound mainloop): block per (j, group of IG=4 i-rows),
// 512 threads: each thread owns exactly one float4 column slot (no it-loop),
// mu/scale in 8 registers. 4 independent row streams for MLP, low regs ->
// high occupancy.
//   p[i,j,:] = mu[j,:] + eps[i,j,:] * scale[j,:]
//   log_prob[i,j] = -0.5 * sum(eps^2) - 0.25*sum(lv[j]) - 0.5*D*log2pi
// grid = B*(B/IG) = 9216 blocks x 512 threads.
// ---------------------------------------------------------------------------
__global__ void __launch_bounds__(512) main_kernel(
    const float* __restrict__ eps,
    float* __restrict__ p,
    float* __restrict__ lp)
{
    __shared__ float red[16][IG];
    __shared__ float s_t;

    int j   = blockIdx.x % B;
    int ig  = blockIdx.x / B;        // 0..47
    int tid = threadIdx.x;           // 0..511 == float4 slot

    const float4* m4 = (const float4*)g_mu    + (size_t)j * (D / 4);
    const float4* s4 = (const float4*)g_scale + (size_t)j * (D / 4);
    float4 m = m4[tid];
    float4 s = s4[tid];

    if (tid == 0) {
        float sum = 0.f;
        #pragma unroll
        for (int k = 0; k < 8; ++k) sum += g_lvpart[j * 8 + k];
        s_t = -0.25f * sum - 0.5f * (float)D * LOG2PI;
    }

    float acc[IG];
    #pragma unroll
    for (int r = 0; r < IG; ++r) {
        size_t row = (size_t)(ig * IG + r) * B + j;
        const float4* e4 = (const float4*)eps + row * (D / 4);
        float4*       p4 = (float4*)p        + row * (D / 4);

        float4 e = __ldcs(&e4[tid]);
        float4 o;
        o.x = fmaf(e.x, s.x, m.x);
        o.y = fmaf(e.y, s.y, m.y);
        o.z = fmaf(e.z, s.z, m.z);
        o.w = fmaf(e.w, s.w, m.w);
        __stcs(&p4[tid], o);
        acc[r] = e.x * e.x + e.y * e.y + e.z * e.z + e.w * e.w;
    }

    int lane = tid & 31, wid = tid >> 5;
    #pragma unroll
    for (int r = 0; r < IG; ++r) {
        float v = acc[r];
        #pragma unroll
        for (int o = 16; o; o >>= 1) v += __shfl_xor_sync(0xffffffffu, v, o);
        if (lane == 0) red[wid][r] = v;
    }
    __syncthreads();
    if (tid < IG) {
        float v = 0.f;
        #pragma unroll
        for (int k = 0; k < 16; ++k) v += red[k][tid];
        lp[(size_t)(ig * IG + tid) * B + j] = -0.5f * v + s_t;
    }
}

// ---------------------------------------------------------------------------
extern "C" void kernel_launch(void* const* d_in, const int* in_sizes, int n_in,
                              void* d_out, int out_size)
{
    const float* q     = (const float*)d_in[0];
    const float* eps   = (const float*)d_in[1];
    const float* mu_w1 = (const float*)d_in[2];
    const float* mu_b1 = (const float*)d_in[3];
    const float* mu_w2 = (const float*)d_in[4];
    const float* mu_b2 = (const float*)d_in[5];
    const float* mu_w3 = (const float*)d_in[6];
    const float* mu_b3 = (const float*)d_in[7];
    const float* lv_w1 = (const float*)d_in[8];
    const float* lv_b1 = (const float*)d_in[9];
    const float* lv_w2 = (const float*)d_in[10];
    const float* lv_b2 = (const float*)d_in[11];
    const float* lv_w3 = (const float*)d_in[12];
    const float* lv_b3 = (const float*)d_in[13];

    float* p  = (float*)d_out;                       // [B, B, D]
    float* lp = (float*)d_out + (size_t)B * B * D;   // [B, B]

    gemm1_kernel<<<dim3(8, 24), 256>>>(q, mu_w1, mu_b1, lv_w1, lv_b1);
    gemm2_kernel<<<B / 8, 256>>>(mu_w2, mu_b2, lv_w2, lv_b2);
    gemm3_kernel<<<dim3(16, 24), 256>>>(mu_w3, mu_b3, lv_w3, lv_b3);
    main_kernel<<<B * (B / IG), 512>>>(eps, p, lp);
}

// round 6
// speedup vs baseline: 1.0748x; 1.0748x over previous
#include <cuda_runtime.h>
#include <math.h>

#define B 192
#define D 2048
#define H 128
#define LOG2PI 1.8378770664093453f
#define IG 4   // i-rows per main-kernel block

// Scratch (device globals — no allocation allowed)
__device__ __align__(16) float g_h1p[2][B * 2 * H];   // split-K partials
__device__ __align__(16) float g_h2[B * 2 * H];
__device__ __align__(16) float g_mu[B * D];
__device__ __align__(16) float g_scale[B * D];
__device__ float g_lvpart[B * 8];

// ---------------------------------------------------------------------------
// Kernel 1: raw partial dot products for layer 1, both heads.
// 8x4 register-tiled warps, split-K x2: block z handles K range [z*1024, +1024).
// grid = (8 colgroups, 24 rowgroups, 2 kchunks) x 256 threads = 384 blocks.
// Bias + ReLU deferred to gemm2 (needs the cross-chunk sum).
// ---------------------------------------------------------------------------
__global__ void __launch_bounds__(256) gemm1_kernel(
    const float* __restrict__ q,
    const float* __restrict__ mw,
    const float* __restrict__ lw)
{
    int warp = threadIdx.x >> 5;
    int lane = threadIdx.x & 31;
    int cg   = blockIdx.x * 8 + warp;   // colgroup 0..63
    int row0 = blockIdx.y * 8;
    int col0 = cg * 4;
    int kz   = blockIdx.z;              // 0 or 1
    int kbase = kz * (D / 4 / 2);       // in float4 units: 0 or 256

    const float* wbase;
    int clocal;
    if (col0 < H) { wbase = mw; clocal = col0;     }
    else          { wbase = lw; clocal = col0 - H; }

    const float4* q4 = (const float4*)q;
    const float4* w4 = (const float4*)wbase;

    float acc[8][4];
    #pragma unroll
    for (int r = 0; r < 8; ++r)
        #pragma unroll
        for (int c = 0; c < 4; ++c) acc[r][c] = 0.f;

    #pragma unroll 4
    for (int it = 0; it < 8; ++it) {   // 8 iters x 32 lanes x float4 = 1024 K
        int k4 = kbase + lane + it * 32;
        float4 b[4];
        #pragma unroll
        for (int c = 0; c < 4; ++c) b[c] = w4[(size_t)(clocal + c) * (D / 4) + k4];
        #pragma unroll
        for (int r = 0; r < 8; ++r) {
            float4 a = q4[(size_t)(row0 + r) * (D / 4) + k4];
            #pragma unroll
            for (int c = 0; c < 4; ++c)
                acc[r][c] += a.x * b[c].x + a.y * b[c].y
                           + a.z * b[c].z + a.w * b[c].w;
        }
    }

    #pragma unroll
    for (int r = 0; r < 8; ++r)
        #pragma unroll
        for (int c = 0; c < 4; ++c) {
            float v = acc[r][c];
            #pragma unroll
            for (int o = 16; o; o >>= 1) v += __shfl_xor_sync(0xffffffffu, v, o);
            if (lane == 0)
                g_h1p[kz][(row0 + r) * 256 + col0 + c] = v;
        }
}

// ---------------------------------------------------------------------------
// Kernel 2: h1 = relu(part0 + part1 + b1); h2 = relu(h1 @ w2^T + b2).
// 8 rows per block (24 blocks). Layer-1 biases applied here.
// ---------------------------------------------------------------------------
__global__ void __launch_bounds__(256) gemm2_kernel(
    const float* __restrict__ mb1, const float* __restrict__ lb1,
    const float* __restrict__ mw, const float* __restrict__ mb,
    const float* __restrict__ lw, const float* __restrict__ lb)
{
    __shared__ float s[8][256];
    int row0 = blockIdx.x * 8;
    int tid = threadIdx.x;

    float b1 = (tid < H) ? mb1[tid] : lb1[tid - H];
    #pragma unroll
    for (int r = 0; r < 8; ++r)
        s[r][tid] = fmaxf(g_h1p[0][(row0 + r) * 256 + tid]
                        + g_h1p[1][(row0 + r) * 256 + tid] + b1, 0.f);
    __syncthreads();

    const float* w;
    float bias;
    int hoff;
    if (tid < H) { w = mw + (size_t)tid * H;       bias = mb[tid];     hoff = 0; }
    else         { w = lw + (size_t)(tid - H) * H; bias = lb[tid - H]; hoff = H; }

    float acc[8];
    #pragma unroll
    for (int r = 0; r < 8; ++r) acc[r] = bias;

    #pragma unroll 8
    for (int k = 0; k < H; ++k) {
        float wv = w[k];
        #pragma unroll
        for (int r = 0; r < 8; ++r) acc[r] += s[r][hoff + k] * wv;
    }
    #pragma unroll
    for (int r = 0; r < 8; ++r)
        g_h2[(row0 + r) * 256 + tid] = fmaxf(acc[r], 0.f);
}

// ---------------------------------------------------------------------------
// Kernel 3: layer-3 for both heads, 8 rows per block, h2 half-rows in smem.
//   mu head  (bx 0..7):  g_mu = relu(...)
//   lv head  (bx 8..15): g_scale = exp(0.25*lv), deterministic partial sum(lv)
// ---------------------------------------------------------------------------
__global__ void __launch_bounds__(256) gemm3_kernel(
    const float* __restrict__ mw, const float* __restrict__ mb,
    const float* __restrict__ lw, const float* __restrict__ lb)
{
    __shared__ float4 s4[8][32];
    __shared__ float red[8][8];

    int tid  = threadIdx.x;
    int row0 = blockIdx.y * 8;
    int head = blockIdx.x >> 3;        // 0 = mu, 1 = lv

    {
        int r  = tid >> 5;
        int kk = tid & 31;
        s4[r][kk] = ((const float4*)(g_h2 + (row0 + r) * 256 + head * H))[kk];
    }
    __syncthreads();

    int d = (blockIdx.x & 7) * 256 + tid;
    const float* wrow = (head ? lw : mw) + (size_t)d * H;
    const float* bptr = head ? lb : mb;

    float acc[8];
    #pragma unroll
    for (int r = 0; r < 8; ++r) acc[r] = 0.f;

    #pragma unroll
    for (int kk = 0; kk < 32; ++kk) {
        float4 w = ((const float4*)wrow)[kk];
        #pragma unroll
        for (int r = 0; r < 8; ++r) {
            float4 h = s4[r][kk];
            acc[r] += w.x * h.x + w.y * h.y + w.z * h.z + w.w * h.w;
        }
    }
    float bias = bptr[d];

    if (!head) {
        #pragma unroll
        for (int r = 0; r < 8; ++r)
            g_mu[(size_t)(row0 + r) * D + d] = fmaxf(acc[r] + bias, 0.f);
    } else {
        int lane = tid & 31, wid = tid >> 5;
        #pragma unroll
        for (int r = 0; r < 8; ++r) {
            float v = fmaxf(acc[r] + bias, 0.f);
            g_scale[(size_t)(row0 + r) * D + d] = expf(0.25f * v);
            #pragma unroll
            for (int o = 16; o; o >>= 1) v += __shfl_xor_sync(0xffffffffu, v, o);
            if (lane == 0) red[wid][r] = v;
        }
        __syncthreads();
        if (tid == 0) {
            #pragma unroll
            for (int r = 0; r < 8; ++r) {
                float sum = 0.f;
                #pragma unroll
                for (int k = 0; k < 8; ++k) sum += red[k][r];
                g_lvpart[(row0 + r) * 8 + (blockIdx.x & 7)] = sum;
            }
        }
    }
}

// ---------------------------------------------------------------------------
// Kernel 4 (HBM-bound mainloop): R4-exact shape — block per (j, 4 i-rows),
// 256 threads, 2 float4 per thread per row (8 independent loads in flight),
// mu/scale in registers.
// ---------------------------------------------------------------------------
__global__ void __launch_bounds__(256) main_kernel(
    const float* __restrict__ eps,
    float* __restrict__ p,
    float* __restrict__ lp)
{
    __shared__ float red[8][IG];
    __shared__ float s_t;

    int j   = blockIdx.x % B;
    int ig  = blockIdx.x / B;
    int tid = threadIdx.x;

    const float4* m4 = (const float4*)g_mu    + (size_t)j * (D / 4);
    const float4* s4 = (const float4*)g_scale + (size_t)j * (D / 4);
    float4 m0 = m4[tid], m1 = m4[tid + 256];
    float4 s0 = s4[tid], s1 = s4[tid + 256];

    if (tid == 0) {
        float sum = 0.f;
        #pragma unroll
        for (int k = 0; k < 8; ++k) sum += g_lvpart[j * 8 + k];
        s_t = -0.25f * sum - 0.5f * (float)D * LOG2PI;
    }

    float acc[IG];
    #pragma unroll
    for (int r = 0; r < IG; ++r) {
        size_t row = (size_t)(ig * IG + r) * B + j;
        const float4* e4 = (const float4*)eps + row * (D / 4);
        float4*       p4 = (float4*)p        + row * (D / 4);

        float4 e0 = __ldcs(&e4[tid]);
        float4 e1 = __ldcs(&e4[tid + 256]);
        float4 o0, o1;
        o0.x = fmaf(e0.x, s0.x, m0.x);
        o0.y = fmaf(e0.y, s0.y, m0.y);
        o0.z = fmaf(e0.z, s0.z, m0.z);
        o0.w = fmaf(e0.w, s0.w, m0.w);
        o1.x = fmaf(e1.x, s1.x, m1.x);
        o1.y = fmaf(e1.y, s1.y, m1.y);
        o1.z = fmaf(e1.z, s1.z, m1.z);
        o1.w = fmaf(e1.w, s1.w, m1.w);
        __stcs(&p4[tid], o0);
        __stcs(&p4[tid + 256], o1);
        acc[r] = e0.x * e0.x + e0.y * e0.y + e0.z * e0.z + e0.w * e0.w
               + e1.x * e1.x + e1.y * e1.y + e1.z * e1.z + e1.w * e1.w;
    }

    int lane = tid & 31, wid = tid >> 5;
    #pragma unroll
    for (int r = 0; r < IG; ++r) {
        float v = acc[r];
        #pragma unroll
        for (int o = 16; o; o >>= 1) v += __shfl_xor_sync(0xffffffffu, v, o);
        if (lane == 0) red[wid][r] = v;
    }
    __syncthreads();
    if (tid < IG) {
        float v = 0.f;
        #pragma unroll
        for (int k = 0; k < 8; ++k) v += red[k][tid];
        lp[(size_t)(ig * IG + tid) * B + j] = -0.5f * v + s_t;
    }
}

// ---------------------------------------------------------------------------
extern "C" void kernel_launch(void* const* d_in, const int* in_sizes, int n_in,
                              void* d_out, int out_size)
{
    const float* q     = (const float*)d_in[0];
    const float* eps   = (const float*)d_in[1];
    const float* mu_w1 = (const float*)d_in[2];
    const float* mu_b1 = (const float*)d_in[3];
    const float* mu_w2 = (const float*)d_in[4];
    const float* mu_b2 = (const float*)d_in[5];
    const float* mu_w3 = (const float*)d_in[6];
    const float* mu_b3 = (const float*)d_in[7];
    const float* lv_w1 = (const float*)d_in[8];
    const float* lv_b1 = (const float*)d_in[9];
    const float* lv_w2 = (const float*)d_in[10];
    const float* lv_b2 = (const float*)d_in[11];
    const float* lv_w3 = (const float*)d_in[12];
    const float* lv_b3 = (const float*)d_in[13];

    float* p  = (float*)d_out;                       // [B, B, D]
    float* lp = (float*)d_out + (size_t)B * B * D;   // [B, B]

    gemm1_kernel<<<dim3(8, 24, 2), 256>>>(q, mu_w1, lv_w1);
    gemm2_kernel<<<B / 8, 256>>>(mu_b1, lv_b1, mu_w2, mu_b2, lv_w2, lv_b2);
    gemm3_kernel<<<dim3(16, 24), 256>>>(mu_w3, mu_b3, lv_w3, lv_b3);
    main_kernel<<<B * (B / IG), 256>>>(eps, p, lp);
}